// round 1
// baseline (speedup 1.0000x reference)
#include <cuda_runtime.h>
#include <math.h>

#define NTOK 32768      // B * FH * FW = 8 * 64 * 64
#define DIM 768
#define HDIM 3072
#define NHEAD 12
#define HD 64
#define NWIN 128        // K*K*B = 16 * 8
#define WTOK 256        // (FH/K)*(FW/K) = 16*16
#define LAYERS 2
#define EPS 1e-6f

// ---------------- scratch (device globals; no allocations allowed) ----------
__device__ float g_xn[NTOK * DIM];
__device__ float g_q [NTOK * DIM];
__device__ float g_k [NTOK * DIM];
__device__ float g_v [NTOK * DIM];
__device__ float g_ao[NTOK * DIM];
__device__ float g_h [NTOK * HDIM];   // 402 MB MLP hidden

// ---------------- LayerNorm: one warp per row ------------------------------
__global__ void ln_kernel(const float* __restrict__ x, float* __restrict__ y,
                          const float* __restrict__ gamma, const float* __restrict__ beta) {
    int lane = threadIdx.x;
    long row = (long)blockIdx.x * 8 + threadIdx.y;
    const float4* xr = (const float4*)(x + row * DIM);
    float4 vals[6];
    float s = 0.f, s2 = 0.f;
#pragma unroll
    for (int i = 0; i < 6; i++) {
        float4 f = xr[i * 32 + lane];
        vals[i] = f;
        s  += f.x + f.y + f.z + f.w;
        s2 += f.x*f.x + f.y*f.y + f.z*f.z + f.w*f.w;
    }
#pragma unroll
    for (int off = 16; off; off >>= 1) {
        s  += __shfl_xor_sync(0xffffffffu, s,  off);
        s2 += __shfl_xor_sync(0xffffffffu, s2, off);
    }
    float mean = s * (1.f / DIM);
    float var  = s2 * (1.f / DIM) - mean * mean;
    float inv  = rsqrtf(var + EPS);

    float4* yr = (float4*)(y + row * DIM);
    const float4* gg = (const float4*)gamma;
    const float4* bb = (const float4*)beta;
#pragma unroll
    for (int i = 0; i < 6; i++) {
        int c = i * 32 + lane;
        float4 g = gg[c], b = bb[c], v = vals[i], o;
        o.x = (v.x - mean) * inv * g.x + b.x;
        o.y = (v.y - mean) * inv * g.y + b.y;
        o.z = (v.z - mean) * inv * g.z + b.z;
        o.w = (v.w - mean) * inv * g.w + b.w;
        yr[c] = o;
    }
}

// ---------------- GEMM: C = A[MxK] * W[KxN] + bias, epilogue variants ------
// EPI 0: +bias    1: (acc+bias)*alpha    2: +bias+res    3: quickgelu(acc+bias)
#define GBM 128
#define GBN 128
#define GBK 8

template <int EPI>
__global__ void __launch_bounds__(256)
gemm_kernel(const float* __restrict__ A, const float* __restrict__ W,
            const float* __restrict__ bias, const float* res,
            float* C, int M, int K, int N, float alpha) {
    __shared__ float As[GBK][GBM];
    __shared__ float Bs[GBK][GBN];

    int tid = threadIdx.x;
    int tx = tid & 15;   // 0..15 (col group of 8)
    int ty = tid >> 4;   // 0..15 (row group of 8)
    long row0 = (long)blockIdx.y * GBM;
    int  col0 = blockIdx.x * GBN;

    int arow = tid >> 1;          // 0..127
    int akof = (tid & 1) * 4;     // 0 or 4
    int brow = tid >> 5;          // 0..7
    int bcol = (tid & 31) * 4;    // 0..124

    const float* Ap = A + (row0 + arow) * K + akof;
    const float* Wp = W + (long)brow * N + col0 + bcol;

    float acc[8][8];
#pragma unroll
    for (int i = 0; i < 8; i++)
#pragma unroll
        for (int j = 0; j < 8; j++) acc[i][j] = 0.f;

    for (int k0 = 0; k0 < K; k0 += GBK) {
        float4 av = *(const float4*)(Ap + k0);
        float4 bv = *(const float4*)(Wp + (long)k0 * N);
        As[akof + 0][arow] = av.x;
        As[akof + 1][arow] = av.y;
        As[akof + 2][arow] = av.z;
        As[akof + 3][arow] = av.w;
        *(float4*)&Bs[brow][bcol] = bv;
        __syncthreads();
#pragma unroll
        for (int k = 0; k < GBK; k++) {
            float a[8], b[8];
            *(float4*)&a[0] = *(float4*)&As[k][ty * 8];
            *(float4*)&a[4] = *(float4*)&As[k][ty * 8 + 4];
            *(float4*)&b[0] = *(float4*)&Bs[k][tx * 8];
            *(float4*)&b[4] = *(float4*)&Bs[k][tx * 8 + 4];
#pragma unroll
            for (int i = 0; i < 8; i++)
#pragma unroll
                for (int j = 0; j < 8; j++) acc[i][j] += a[i] * b[j];
        }
        __syncthreads();
    }

    float bv[8];
#pragma unroll
    for (int j = 0; j < 8; j++) bv[j] = bias[col0 + tx * 8 + j];

#pragma unroll
    for (int i = 0; i < 8; i++) {
        long base = (row0 + ty * 8 + i) * N + col0 + tx * 8;
#pragma unroll
        for (int j = 0; j < 8; j++) {
            float v = acc[i][j] + bv[j];
            if (EPI == 1) v *= alpha;
            if (EPI == 2) v += res[base + j];
            if (EPI == 3) v = v / (1.f + __expf(-1.702f * v));  // x*sigmoid(1.702x)
            C[base + j] = v;
        }
    }
}

// ---------------- window attention ------------------------------------------
// grid (128 windows, 12 heads), 256 threads; K/V tile in smem, q/o in regs.
// Window slot s: b = s%8, i = (s/8)/4, j = (s/8)%4; token t: h=t/16, w=t%16
// global token n = b*4096 + (i*16+h)*64 + (j*16+w)
__device__ __forceinline__ long attn_row(int widx, int t) {
    int b = widx & 7;
    int ij = widx >> 3;
    int wi = ij >> 2, wj = ij & 3;
    int hh = t >> 4, ww = t & 15;
    return (long)b * 4096 + (wi * 16 + hh) * 64 + (wj * 16 + ww);
}

__global__ void __launch_bounds__(256, 1)
attn_kernel(const float* __restrict__ q, const float* __restrict__ k,
            const float* __restrict__ v, float* __restrict__ ao) {
    extern __shared__ float sm[];
    float* ks = sm;                 // [256][64]
    float* vs = sm + WTOK * HD;     // [256][64]

    int widx = blockIdx.x;
    int head = blockIdx.y;
    int tid = threadIdx.x;

    // load K and V window tiles (4 threads per row, float4)
    int lane4 = tid & 3;
    int rbase = tid >> 2;
#pragma unroll
    for (int rr = 0; rr < 4; rr++) {
        int t = rr * 64 + rbase;
        long grow = attn_row(widx, t) * DIM + head * HD;
#pragma unroll
        for (int i = 0; i < 4; i++) {
            int c = lane4 * 16 + i * 4;
            *(float4*)&ks[t * HD + c] = *(const float4*)&k[grow + c];
            *(float4*)&vs[t * HD + c] = *(const float4*)&v[grow + c];
        }
    }
    __syncthreads();

    // one query row per thread
    long qrow = attn_row(widx, tid) * DIM + head * HD;
    float qr[HD];
#pragma unroll
    for (int d = 0; d < HD; d += 4) {
        float4 f = *(const float4*)&q[qrow + d];
        qr[d] = f.x; qr[d + 1] = f.y; qr[d + 2] = f.z; qr[d + 3] = f.w;
    }

    // pass 1: row max
    float m = -1e30f;
    for (int key = 0; key < WTOK; key++) {
        float s = 0.f;
#pragma unroll
        for (int d = 0; d < HD; d += 4) {
            float4 kk = *(float4*)&ks[key * HD + d];
            s += qr[d] * kk.x + qr[d + 1] * kk.y + qr[d + 2] * kk.z + qr[d + 3] * kk.w;
        }
        m = fmaxf(m, s);
    }

    // pass 2: softmax weights (recomputed scores) + AV accumulation
    float l = 0.f;
    float o[HD];
#pragma unroll
    for (int d = 0; d < HD; d++) o[d] = 0.f;

    for (int key = 0; key < WTOK; key++) {
        float s = 0.f;
#pragma unroll
        for (int d = 0; d < HD; d += 4) {
            float4 kk = *(float4*)&ks[key * HD + d];
            s += qr[d] * kk.x + qr[d + 1] * kk.y + qr[d + 2] * kk.z + qr[d + 3] * kk.w;
        }
        float p = __expf(s - m);
        l += p;
#pragma unroll
        for (int d = 0; d < HD; d += 4) {
            float4 vv = *(float4*)&vs[key * HD + d];
            o[d]     += p * vv.x;
            o[d + 1] += p * vv.y;
            o[d + 2] += p * vv.z;
            o[d + 3] += p * vv.w;
        }
    }

    float inv = 1.f / l;
#pragma unroll
    for (int d = 0; d < HD; d += 4) {
        float4 f;
        f.x = o[d] * inv; f.y = o[d + 1] * inv;
        f.z = o[d + 2] * inv; f.w = o[d + 3] * inv;
        *(float4*)&ao[qrow + d] = f;
    }
}

// ---------------- host ------------------------------------------------------
extern "C" void kernel_launch(void* const* d_in, const int* in_sizes, int n_in,
                              void* d_out, int out_size) {
    const float* x    = (const float*)d_in[0];
    const float* ln1s = (const float*)d_in[1];
    const float* ln1b = (const float*)d_in[2];
    const float* Wq   = (const float*)d_in[3];
    const float* bq   = (const float*)d_in[4];
    const float* Wk   = (const float*)d_in[5];
    const float* bk   = (const float*)d_in[6];
    const float* Wv   = (const float*)d_in[7];
    const float* bv   = (const float*)d_in[8];
    const float* Wo   = (const float*)d_in[9];
    const float* bo   = (const float*)d_in[10];
    const float* ln2s = (const float*)d_in[11];
    const float* ln2b = (const float*)d_in[12];
    const float* W1   = (const float*)d_in[13];
    const float* b1   = (const float*)d_in[14];
    const float* W2   = (const float*)d_in[15];
    const float* b2   = (const float*)d_in[16];
    float* out = (float*)d_out;

    float *xn, *qb, *kb, *vb, *aob, *hb;
    cudaGetSymbolAddress((void**)&xn,  g_xn);
    cudaGetSymbolAddress((void**)&qb,  g_q);
    cudaGetSymbolAddress((void**)&kb,  g_k);
    cudaGetSymbolAddress((void**)&vb,  g_v);
    cudaGetSymbolAddress((void**)&aob, g_ao);
    cudaGetSymbolAddress((void**)&hb,  g_h);

    int attn_smem = 2 * WTOK * HD * (int)sizeof(float);  // 128 KB
    cudaFuncSetAttribute(attn_kernel, cudaFuncAttributeMaxDynamicSharedMemorySize, attn_smem);

    // residual stream lives in d_out; window permutation is identity end-to-end
    cudaMemcpyAsync(out, x, (size_t)NTOK * DIM * sizeof(float),
                    cudaMemcpyDeviceToDevice, 0);

    dim3 lnGrid(NTOK / 8), lnBlk(32, 8);
    dim3 gD(DIM / GBN,  NTOK / GBM);   // 6 x 256
    dim3 gH(HDIM / GBN, NTOK / GBM);   // 24 x 256

    for (int l = 0; l < LAYERS; l++) {
        const float* Wq_l = Wq + (long)l * DIM * DIM;
        const float* Wk_l = Wk + (long)l * DIM * DIM;
        const float* Wv_l = Wv + (long)l * DIM * DIM;
        const float* Wo_l = Wo + (long)l * DIM * DIM;
        const float* W1_l = W1 + (long)l * DIM * HDIM;
        const float* W2_l = W2 + (long)l * HDIM * DIM;

        ln_kernel<<<lnGrid, lnBlk>>>(out, xn, ln1s + l * DIM, ln1b + l * DIM);

        gemm_kernel<1><<<gD, 256>>>(xn, Wq_l, bq + l * DIM, nullptr, qb,
                                    NTOK, DIM, DIM, 0.125f);
        gemm_kernel<0><<<gD, 256>>>(xn, Wk_l, bk + l * DIM, nullptr, kb,
                                    NTOK, DIM, DIM, 1.f);
        gemm_kernel<0><<<gD, 256>>>(xn, Wv_l, bv + l * DIM, nullptr, vb,
                                    NTOK, DIM, DIM, 1.f);

        attn_kernel<<<dim3(NWIN, NHEAD), 256, attn_smem>>>(qb, kb, vb, aob);

        gemm_kernel<2><<<gD, 256>>>(aob, Wo_l, bo + l * DIM, out, out,
                                    NTOK, DIM, DIM, 1.f);

        ln_kernel<<<lnGrid, lnBlk>>>(out, xn, ln2s + l * DIM, ln2b + l * DIM);

        gemm_kernel<3><<<gH, 256>>>(xn, W1_l, b1 + l * HDIM, nullptr, hb,
                                    NTOK, DIM, HDIM, 1.f);
        gemm_kernel<2><<<gD, 256>>>(hb, W2_l, b2 + l * DIM, out, out,
                                    NTOK, HDIM, DIM, 1.f);
    }
}